// round 16
// baseline (speedup 1.0000x reference)
#include <cuda_runtime.h>
#include <math.h>
#include <stdint.h>

// ---------------------------------------------------------------------------
// Problem constants
// ---------------------------------------------------------------------------
#define BB 16
#define MM 2048
#define FD 128
#define TSQ 128                      // q rows per item
#define TSK 64                       // k cols per item
#define NT 16                        // q tiles per batch
#define NPAIR 136                    // tile pairs (ti <= tj)
#define ITEMS_PER_B (NPAIR * 2)      // 272 (pair x chunk)
#define TOTAL_ITEMS (BB * ITEMS_PER_B)   // 4352
#define NCTA 296                     // 2 CTAs/SM x 148 SMs, single wave
#define QSTRIDE 128                  // unpadded: q-loads are broadcasts
#define KSTRIDE 132                  // padded: conflict-free k-loads
// smem layout (floats): Q[128*128] | K[64*132] | cand[1024 float2]
#define SMF_Q 0
#define SMF_K (TSQ * QSTRIDE)                 // 16384
#define SMF_CAND (SMF_K + TSK * KSTRIDE)      // 24832
#define SMEM_BYTES ((SMF_CAND + 2048) * 4)    // 107520 -> 2 CTAs/SM
#define ZCHUNK 15424                 // 272 * 15424 >= 2048*2048

// Scratch (device globals; no allocation allowed)
__device__ __align__(128) float  g_xnorm[BB * MM * FD];
// Candidates: [b*M + row][slot(32)][2] float2 {val, idx-bits}
__device__ __align__(128) float2 g_cand[(size_t)BB * MM * 32 * 2];

// ---------------------------------------------------------------------------
__device__ __forceinline__ uint32_t smem_u32(const void* p) {
    uint32_t a;
    asm("{ .reg .u64 t; cvta.to.shared.u64 t, %1; cvt.u32.u64 %0, t; }"
        : "=r"(a) : "l"(p));
    return a;
}

__device__ __forceinline__ void cp16(uint32_t dst, const void* src) {
    asm volatile("cp.async.ca.shared.global [%0], [%1], 16;" :: "r"(dst), "l"(src));
}

__device__ __forceinline__ unsigned long long fma2(unsigned long long a,
                                                   unsigned long long b,
                                                   unsigned long long c) {
    unsigned long long d;
    asm("fma.rn.f32x2 %0, %1, %2, %3;" : "=l"(d) : "l"(a), "l"(b), "l"(c));
    return d;
}

__device__ __forceinline__ float fold2(unsigned long long v) {
    float lo = __uint_as_float((unsigned)(v & 0xffffffffull));
    float hi = __uint_as_float((unsigned)(v >> 32));
    return lo + hi;
}

// top-2 update, jax tie-break (equal value -> lower index); candidates distinct
__device__ __forceinline__ void top2_update(float v, int k,
                                            float& v1, int& i1, float& v2, int& i2) {
    bool b1 = (v > v1) || (v == v1 && k < i1);
    bool b2 = (v > v2) || (v == v2 && k < i2);
    if (b1)      { v2 = v1; i2 = i1; v1 = v; i1 = k; }
    else if (b2) { v2 = v;  i2 = k; }
}

// merge with index-dedup (butterfly partners carry identical winners)
__device__ __forceinline__ void top2_merge(float v, int k,
                                           float& v1, int& i1, float& v2, int& i2) {
    if (k == i1 || k == i2) return;
    top2_update(v, k, v1, i1, v2, i2);
}

__device__ __forceinline__ void decode_item(int item, int& b, int& ti, int& tj, int& ch) {
    b = item / ITEMS_PER_B;
    int r = item - b * ITEMS_PER_B;
    ch = r & 1;
    int p = r >> 1, n = NT; ti = 0;
    while (p >= n) { p -= n; n--; ti++; }
    tj = ti + p;
}

// ---------------------------------------------------------------------------
// Kernel 1: L2-normalize each row (one warp per row)
// ---------------------------------------------------------------------------
__global__ void normalize_kernel(const float* __restrict__ x) {
    int row  = blockIdx.x * 8 + (threadIdx.x >> 5);
    int lane = threadIdx.x & 31;
    float4 v = reinterpret_cast<const float4*>(x + (size_t)row * FD)[lane];
    float ss = v.x * v.x + v.y * v.y + v.z * v.z + v.w * v.w;
    #pragma unroll
    for (int o = 16; o > 0; o >>= 1) ss += __shfl_xor_sync(0xffffffffu, ss, o);
    float inv = 1.0f / fmaxf(sqrtf(ss), 1e-12f);
    v.x *= inv; v.y *= inv; v.z *= inv; v.w *= inv;
    reinterpret_cast<float4*>(g_xnorm + (size_t)row * FD)[lane] = v;
}

// ---------------------------------------------------------------------------
// Kernel 2: persistent symmetric tile-pair GEMM. 296 CTAs, ~15 items each.
// Q tile cached across items sharing (b, ti); next K prefetched via cp.async
// during the epilogue. Per item: 128(q) x 64(k), 8x4 micro-tile, 2 CTAs/SM.
// ---------------------------------------------------------------------------
__global__ void __launch_bounds__(256, 2) pair_kernel(float* __restrict__ out) {
    extern __shared__ float smem[];
    float*  Qs   = smem + SMF_Q;           // [128][QSTRIDE]
    float*  Ks   = smem + SMF_K;           // [64][KSTRIDE]
    float2* cand = reinterpret_cast<float2*>(smem + SMF_CAND);  // 1024 float2
    const uint32_t sQ = smem_u32(Qs);
    const uint32_t sK = smem_u32(Ks);

    const int tid = threadIdx.x;
    const int tx  = tid & 15;
    const int ty  = tid >> 4;

    const int lo = (int)((long long)blockIdx.x * TOTAL_ITEMS / NCTA);
    const int hi = (int)((long long)(blockIdx.x + 1) * TOTAL_ITEMS / NCTA);

    int b, ti, tj, ch;
    decode_item(lo, b, ti, tj, ch);

    // ---- synchronous initial tile loads ----
    {
        const float* Xb = g_xnorm + (size_t)b * MM * FD;
        #pragma unroll
        for (int p = 0; p < 16; p++) {
            int idx = tid + p * 256;
            int r = idx >> 5, c4 = idx & 31;
            float4 v = reinterpret_cast<const float4*>(Xb + (size_t)(ti * TSQ + r) * FD)[c4];
            *reinterpret_cast<float4*>(Qs + r * QSTRIDE + c4 * 4) = v;
        }
        int kb0 = tj * TSQ + ch * TSK;
        #pragma unroll
        for (int p = 0; p < 8; p++) {
            int idx = tid + p * 256;
            int r = idx >> 5, c4 = idx & 31;
            float4 v = reinterpret_cast<const float4*>(Xb + (size_t)(kb0 + r) * FD)[c4];
            *reinterpret_cast<float4*>(Ks + r * KSTRIDE + c4 * 4) = v;
        }
    }
    __syncthreads();

    for (int it = lo; it < hi; ++it) {
        const int ibase = ti * TSQ;
        const int kbase = tj * TSQ + ch * TSK;

        // ---- mainloop: 8x4 micro-tile, packed-f32x2 accumulation ----
        unsigned long long acc2[8][4];
        #pragma unroll
        for (int i = 0; i < 8; i++)
            #pragma unroll
            for (int j = 0; j < 4; j++) acc2[i][j] = 0ull;

        #pragma unroll 2
        for (int f = 0; f < FD; f += 4) {
            ulonglong2 k2[4];
            #pragma unroll
            for (int j = 0; j < 4; j++)
                k2[j] = *reinterpret_cast<const ulonglong2*>(Ks + (tx + 16 * j) * KSTRIDE + f);
            #pragma unroll
            for (int half = 0; half < 2; half++) {
                ulonglong2 q2[4];
                #pragma unroll
                for (int i = 0; i < 4; i++)
                    q2[i] = *reinterpret_cast<const ulonglong2*>(
                        Qs + (ty + 16 * (half * 4 + i)) * QSTRIDE + f);
                #pragma unroll
                for (int i = 0; i < 4; i++) {
                    #pragma unroll
                    for (int j = 0; j < 4; j++) {
                        acc2[half * 4 + i][j] = fma2(q2[i].x, k2[j].x, acc2[half * 4 + i][j]);
                        acc2[half * 4 + i][j] = fma2(q2[i].y, k2[j].y, acc2[half * 4 + i][j]);
                    }
                }
            }
        }

        float acc[8][4];
        #pragma unroll
        for (int i = 0; i < 8; i++)
            #pragma unroll
            for (int j = 0; j < 4; j++) acc[i][j] = fold2(acc2[i][j]);

        if (ti == tj) {   // zero the diagonal
            #pragma unroll
            for (int i = 0; i < 8; i++)
                #pragma unroll
                for (int j = 0; j < 4; j++)
                    if (ty + 16 * i == ch * TSK + tx + 16 * j) acc[i][j] = 0.0f;
        }

        __syncthreads();   // all warps past mainloop: K area free, cand free

        // ---- prefetch next item's K (and Q if tile changes) ----
        int nb = b, nti = ti, ntj = tj, nch = ch;
        const bool havenext = (it + 1 < hi);
        if (havenext) {
            decode_item(it + 1, nb, nti, ntj, nch);
            const float* XbN = g_xnorm + (size_t)nb * MM * FD;
            const int nkb = ntj * TSQ + nch * TSK;
            #pragma unroll
            for (int p = 0; p < 8; p++) {
                int idx = tid + p * 256;
                int r = idx >> 5, c4 = idx & 31;
                cp16(sK + (uint32_t)(r * KSTRIDE + c4 * 4) * 4,
                     XbN + (size_t)(nkb + r) * FD + c4 * 4);
            }
            if (nb != b || nti != ti) {
                #pragma unroll
                for (int p = 0; p < 16; p++) {
                    int idx = tid + p * 256;
                    int r = idx >> 5, c4 = idx & 31;
                    cp16(sQ + (uint32_t)(r * QSTRIDE + c4 * 4) * 4,
                         XbN + (size_t)(nti * TSQ + r) * FD + c4 * 4);
                }
            }
            asm volatile("cp.async.commit_group;" ::: "memory");
        }

        // ---- Pass 1: row-wise top-2. Register pre-merge over tx (2 steps) ----
        {
            float v1[8], v2[8]; int i1[8], i2[8];
            #pragma unroll
            for (int i = 0; i < 8; i++) {
                v1[i] = -INFINITY; v2[i] = -INFINITY;
                i1[i] = 0x7fffffff; i2[i] = 0x7fffffff;
                #pragma unroll
                for (int j = 0; j < 4; j++)
                    top2_update(acc[i][j], kbase + tx + 16 * j, v1[i], i1[i], v2[i], i2[i]);
            }
            #pragma unroll
            for (int o = 1; o <= 2; o <<= 1) {   // partners share ty -> same rows
                #pragma unroll
                for (int i = 0; i < 8; i++) {
                    float a1 = __shfl_xor_sync(0xffffffffu, v1[i], o);
                    int   c1 = __shfl_xor_sync(0xffffffffu, i1[i], o);
                    float a2 = __shfl_xor_sync(0xffffffffu, v2[i], o);
                    int   c2 = __shfl_xor_sync(0xffffffffu, i2[i], o);
                    top2_update(a1, c1, v1[i], i1[i], v2[i], i2[i]);
                    top2_update(a2, c2, v1[i], i1[i], v2[i], i2[i]);
                }
            }
            if ((tx & 3) == 0) {
                #pragma unroll
                for (int i = 0; i < 8; i++) {
                    int row = ty + 16 * i;
                    cand[row * 8 + (tx >> 2) * 2 + 0] = make_float2(v1[i], __int_as_float(i1[i]));
                    cand[row * 8 + (tx >> 2) * 2 + 1] = make_float2(v2[i], __int_as_float(i2[i]));
                }
            }
        }
        __syncthreads();
        {
            // 2 threads/row scan 4 disjoint entries each, shfl merge
            const int row = tid >> 1, half = tid & 1;
            float V1 = -INFINITY, V2 = -INFINITY;
            int   I1 = 0x7fffffff, I2 = 0x7fffffff;
            #pragma unroll
            for (int c = 0; c < 4; c++) {
                float2 e = cand[row * 8 + half * 4 + c];
                top2_update(e.x, __float_as_int(e.y), V1, I1, V2, I2);
            }
            float oV1 = __shfl_xor_sync(0xffffffffu, V1, 1);
            float oV2 = __shfl_xor_sync(0xffffffffu, V2, 1);
            int   oI1 = __shfl_xor_sync(0xffffffffu, I1, 1);
            int   oI2 = __shfl_xor_sync(0xffffffffu, I2, 1);
            top2_update(oV1, oI1, V1, I1, V2, I2);
            top2_update(oV2, oI2, V1, I1, V2, I2);
            if (half == 0) {
                size_t base = ((size_t)(b * MM + ibase + row) * 32 + (2 * tj + ch)) * 2;
                g_cand[base]     = make_float2(V1, __int_as_float(I1));
                g_cand[base + 1] = make_float2(V2, __int_as_float(I2));
            }
        }
        __syncthreads();

        // ---- Pass 2: col-wise top-2 (ti != tj). Pre-merge over ty-parity ----
        if (ti != tj) {
            {
                float w1[4], w2[4]; int j1[4], j2[4];
                #pragma unroll
                for (int j = 0; j < 4; j++) {
                    w1[j] = -INFINITY; w2[j] = -INFINITY;
                    j1[j] = 0x7fffffff; j2[j] = 0x7fffffff;
                    #pragma unroll
                    for (int i = 0; i < 8; i++)
                        top2_update(acc[i][j], ibase + ty + 16 * i, w1[j], j1[j], w2[j], j2[j]);
                }
                #pragma unroll
                for (int j = 0; j < 4; j++) {   // lane^16: same tx, ty parity partner
                    float a1 = __shfl_xor_sync(0xffffffffu, w1[j], 16);
                    int   c1 = __shfl_xor_sync(0xffffffffu, j1[j], 16);
                    float a2 = __shfl_xor_sync(0xffffffffu, w2[j], 16);
                    int   c2 = __shfl_xor_sync(0xffffffffu, j2[j], 16);
                    top2_update(a1, c1, w1[j], j1[j], w2[j], j2[j]);
                    top2_update(a2, c2, w1[j], j1[j], w2[j], j2[j]);
                }
                if ((ty & 1) == 0) {
                    #pragma unroll
                    for (int j = 0; j < 4; j++) {
                        int col = tx + 16 * j;
                        cand[col * 16 + (ty >> 1) * 2 + 0] = make_float2(w1[j], __int_as_float(j1[j]));
                        cand[col * 16 + (ty >> 1) * 2 + 1] = make_float2(w2[j], __int_as_float(j2[j]));
                    }
                }
            }
            __syncthreads();
            if (tid < 128) {
                const int col = tid >> 1, half = tid & 1;
                float V1 = -INFINITY, V2 = -INFINITY;
                int   I1 = 0x7fffffff, I2 = 0x7fffffff;
                #pragma unroll
                for (int c = 0; c < 8; c++) {
                    float2 e = cand[col * 16 + half * 8 + c];
                    top2_update(e.x, __float_as_int(e.y), V1, I1, V2, I2);
                }
                float oV1 = __shfl_xor_sync(0xffffffffu, V1, 1);
                float oV2 = __shfl_xor_sync(0xffffffffu, V2, 1);
                int   oI1 = __shfl_xor_sync(0xffffffffu, I1, 1);
                int   oI2 = __shfl_xor_sync(0xffffffffu, I2, 1);
                top2_update(oV1, oI1, V1, I1, V2, I2);
                top2_update(oV2, oI2, V1, I1, V2, I2);
                if (half == 0) {
                    size_t base = ((size_t)(b * MM + kbase + col) * 32 + ti) * 2;
                    g_cand[base]     = make_float2(V1, __int_as_float(I1));
                    g_cand[base + 1] = make_float2(V2, __int_as_float(I2));
                }
            }
        }

        // ---- zero-fill this item's output slice (overlaps cp.async drain) ----
        {
            const int slice = it - b * ITEMS_PER_B;
            float* O = out + (size_t)b * MM * MM;
            size_t beg = (size_t)slice * ZCHUNK;
            size_t end = beg + ZCHUNK;
            if (end > (size_t)MM * MM) end = (size_t)MM * MM;
            const float4 z = make_float4(0.f, 0.f, 0.f, 0.f);
            #pragma unroll 4
            for (size_t zi = beg + (size_t)tid * 4; zi < end; zi += 256 * 4)
                *reinterpret_cast<float4*>(O + zi) = z;
        }

        asm volatile("cp.async.wait_group 0;" ::: "memory");
        __syncthreads();
        b = nb; ti = nti; tj = ntj; ch = nch;
    }
}

// ---------------------------------------------------------------------------
// Kernel 3: per-row reduce of candidate slots -> top-2 -> symmetric scatter.
// Valid slots for row in tile t: [0, t) from pass-2, [2t, 32) from pass-1.
// ---------------------------------------------------------------------------
__global__ void reduce_kernel(float* __restrict__ out) {
    int row  = blockIdx.x * 8 + (threadIdx.x >> 5);
    int lane = threadIdx.x & 31;
    int m = row & (MM - 1);
    int t = m >> 7;

    float v1 = -INFINITY, v2 = -INFINITY;
    int   i1 = 0x7fffffff, i2 = 0x7fffffff;
    bool valid = (lane < t) || (lane >= 2 * t);
    if (valid) {
        float4 c = reinterpret_cast<const float4*>(g_cand)[(size_t)row * 32 + lane];
        v1 = c.x; i1 = __float_as_int(c.y);
        top2_update(c.z, __float_as_int(c.w), v1, i1, v2, i2);
    }
    #pragma unroll
    for (int o = 16; o > 0; o >>= 1) {
        float ov1 = __shfl_xor_sync(0xffffffffu, v1, o);
        float ov2 = __shfl_xor_sync(0xffffffffu, v2, o);
        int   oi1 = __shfl_xor_sync(0xffffffffu, i1, o);
        int   oi2 = __shfl_xor_sync(0xffffffffu, i2, o);
        top2_merge(ov1, oi1, v1, i1, v2, i2);
        top2_merge(ov2, oi2, v1, i1, v2, i2);
    }
    if (lane == 0) {
        int b = row >> 11;
        float* O = out + (size_t)b * MM * MM;
        atomicAdd(O + (size_t)m * MM + i1, 0.5f * v1);
        atomicAdd(O + (size_t)i1 * MM + m, 0.5f * v1);
        atomicAdd(O + (size_t)m * MM + i2, 0.5f * v2);
        atomicAdd(O + (size_t)i2 * MM + m, 0.5f * v2);
    }
}

// ---------------------------------------------------------------------------
extern "C" void kernel_launch(void* const* d_in, const int* in_sizes, int n_in,
                              void* d_out, int out_size) {
    const float* x = (const float*)d_in[0];
    float* out = (float*)d_out;

    normalize_kernel<<<(BB * MM) / 8, 256>>>(x);

    cudaFuncSetAttribute(pair_kernel,
                         cudaFuncAttributeMaxDynamicSharedMemorySize, SMEM_BYTES);
    pair_kernel<<<NCTA, 256, SMEM_BYTES>>>(out);

    reduce_kernel<<<(BB * MM) / 8, 256>>>(out);
}

// round 17
// speedup vs baseline: 1.1799x; 1.1799x over previous
#include <cuda_runtime.h>
#include <math.h>
#include <stdint.h>

// ---------------------------------------------------------------------------
// Problem constants
// ---------------------------------------------------------------------------
#define BB 16
#define MM 2048
#define FD 128
#define TSQ 128                      // q rows per CTA
#define TSK 64                       // k cols per CTA (half tile)
#define NT (MM / TSQ)                // 16 tiles
#define NPAIR (NT * (NT + 1) / 2)    // 136 tile pairs (ti <= tj)
#define SSTRIDE 132                  // floats per smem row (128 + 4 pad)
#define SMEM_BYTES ((TSQ + TSK) * SSTRIDE * 4)   // 101376 B -> 2 CTAs/SM
// zero-fill slice per CTA: 272 CTAs per batch plane
#define ZCHUNK 15424                 // 272 * 15424 = 4195328 >= 2048*2048

// Scratch (device globals; no allocation allowed)
__device__ __align__(128) float  g_xnorm[BB * MM * FD];       // 16 MB
// Candidates: [b*M + row][slot(32)][2] float2 {val, idx-bits}
__device__ __align__(128) float2 g_cand[(size_t)BB * MM * 32 * 2];   // 16.8 MB

// ---------------------------------------------------------------------------
__device__ __forceinline__ uint32_t smem_u32(const void* p) {
    uint32_t a;
    asm("{ .reg .u64 t; cvta.to.shared.u64 t, %1; cvt.u32.u64 %0, t; }"
        : "=r"(a) : "l"(p));
    return a;
}

__device__ __forceinline__ void cp16(uint32_t dst, const void* src) {
    asm volatile("cp.async.ca.shared.global [%0], [%1], 16;" :: "r"(dst), "l"(src));
}

__device__ __forceinline__ unsigned long long fma2(unsigned long long a,
                                                   unsigned long long b,
                                                   unsigned long long c) {
    unsigned long long d;
    asm("fma.rn.f32x2 %0, %1, %2, %3;" : "=l"(d) : "l"(a), "l"(b), "l"(c));
    return d;
}

__device__ __forceinline__ float fold2(unsigned long long v) {
    float lo = __uint_as_float((unsigned)(v & 0xffffffffull));
    float hi = __uint_as_float((unsigned)(v >> 32));
    return lo + hi;
}

// top-2 update, jax tie-break (equal value -> lower index); candidates distinct
__device__ __forceinline__ void top2_update(float v, int k,
                                            float& v1, int& i1, float& v2, int& i2) {
    bool b1 = (v > v1) || (v == v1 && k < i1);
    bool b2 = (v > v2) || (v == v2 && k < i2);
    if (b1)      { v2 = v1; i2 = i1; v1 = v; i1 = k; }
    else if (b2) { v2 = v;  i2 = k; }
}

// butterfly-merge variant with index-dedup (for duplicate-carrying partners)
__device__ __forceinline__ void top2_merge(float v, int k,
                                           float& v1, int& i1, float& v2, int& i2) {
    if (k == i1 || k == i2) return;
    top2_update(v, k, v1, i1, v2, i2);
}

// ---------------------------------------------------------------------------
// Kernel 1: L2-normalize each row (one warp per row)
// ---------------------------------------------------------------------------
__global__ void normalize_kernel(const float* __restrict__ x) {
    int row  = blockIdx.x * 8 + (threadIdx.x >> 5);
    int lane = threadIdx.x & 31;
    float4 v = reinterpret_cast<const float4*>(x + (size_t)row * FD)[lane];
    float ss = v.x * v.x + v.y * v.y + v.z * v.z + v.w * v.w;
    #pragma unroll
    for (int o = 16; o > 0; o >>= 1) ss += __shfl_xor_sync(0xffffffffu, ss, o);
    float inv = 1.0f / fmaxf(sqrtf(ss), 1e-12f);
    v.x *= inv; v.y *= inv; v.z *= inv; v.w *= inv;
    reinterpret_cast<float4*>(g_xnorm + (size_t)row * FD)[lane] = v;
}

// ---------------------------------------------------------------------------
// Kernel 2: symmetric tile-pair GEMM, 128(q) x 64(k) per CTA, 8x4 micro-tile.
// Grid: (NPAIR, 2, BB). Block 256 = 16(tx, k) x 16(ty, q). 2 CTAs/SM.
// cp.async tile loads issued first; zero-fill of the output slice runs while
// they are in flight (replaces the memset node).
// ---------------------------------------------------------------------------
__global__ void __launch_bounds__(256, 2) pair_kernel(float* __restrict__ out) {
    extern __shared__ float smem[];
    float* Qs = smem;                      // TSQ x SSTRIDE
    float* Ks = smem + TSQ * SSTRIDE;      // TSK x SSTRIDE

    const int tid   = threadIdx.x;
    const int tx    = tid & 15;
    const int ty    = tid >> 4;
    const int chunk = blockIdx.y;          // which 64-col half of the k tile
    const int b     = blockIdx.z;

    // decode tile pair (ti <= tj)
    int t = blockIdx.x, ti = 0, n = NT;
    while (t >= n) { t -= n; n--; ti++; }
    const int tj    = ti + t;
    const int ibase = ti * TSQ;
    const int kbase = tj * TSQ + chunk * TSK;

    const float* Xb = g_xnorm + (size_t)b * MM * FD;
    const uint32_t sQ = smem_u32(Qs);
    const uint32_t sK = smem_u32(Ks);

    // ---- issue async tile loads first ----
    #pragma unroll
    for (int p = 0; p < 16; p++) {
        int idx = tid + p * 256;
        int r = idx >> 5, c4 = idx & 31;
        cp16(sQ + (uint32_t)(r * SSTRIDE + c4 * 4) * 4,
             Xb + (size_t)(ibase + r) * FD + c4 * 4);
    }
    #pragma unroll
    for (int p = 0; p < 8; p++) {
        int idx = tid + p * 256;
        int r = idx >> 5, c4 = idx & 31;
        cp16(sK + (uint32_t)(r * SSTRIDE + c4 * 4) * 4,
             Xb + (size_t)(kbase + r) * FD + c4 * 4);
    }
    asm volatile("cp.async.commit_group;" ::: "memory");

    // ---- zero-fill my slice of out[b] while the copies are in flight ----
    {
        const int cta = blockIdx.x * 2 + chunk;          // 0..271
        float* O = out + (size_t)b * MM * MM;
        size_t beg = (size_t)cta * ZCHUNK;
        size_t end = beg + ZCHUNK;
        if (end > (size_t)MM * MM) end = (size_t)MM * MM;
        const float4 z = make_float4(0.f, 0.f, 0.f, 0.f);
        #pragma unroll 4
        for (size_t i = beg + (size_t)tid * 4; i < end; i += 256 * 4)
            *reinterpret_cast<float4*>(O + i) = z;
    }

    asm volatile("cp.async.wait_group 0;" ::: "memory");
    __syncthreads();

    // 8x4 micro-tile, packed-f32x2 accumulation (pairs along f).
    unsigned long long acc2[8][4];
    #pragma unroll
    for (int i = 0; i < 8; i++)
        #pragma unroll
        for (int j = 0; j < 4; j++) acc2[i][j] = 0ull;

    #pragma unroll 2
    for (int f = 0; f < FD; f += 4) {
        ulonglong2 k2[4];
        #pragma unroll
        for (int j = 0; j < 4; j++)
            k2[j] = *reinterpret_cast<const ulonglong2*>(Ks + (tx + 16 * j) * SSTRIDE + f);
        #pragma unroll
        for (int half = 0; half < 2; half++) {
            ulonglong2 q2[4];
            #pragma unroll
            for (int i = 0; i < 4; i++)
                q2[i] = *reinterpret_cast<const ulonglong2*>(
                    Qs + (ty + 16 * (half * 4 + i)) * SSTRIDE + f);
            #pragma unroll
            for (int i = 0; i < 4; i++) {
                #pragma unroll
                for (int j = 0; j < 4; j++) {
                    acc2[half * 4 + i][j] = fma2(q2[i].x, k2[j].x, acc2[half * 4 + i][j]);
                    acc2[half * 4 + i][j] = fma2(q2[i].y, k2[j].y, acc2[half * 4 + i][j]);
                }
            }
        }
    }

    float acc[8][4];
    #pragma unroll
    for (int i = 0; i < 8; i++)
        #pragma unroll
        for (int j = 0; j < 4; j++) acc[i][j] = fold2(acc2[i][j]);

    // zero the diagonal (only possible within diagonal tile pairs)
    if (ti == tj) {
        #pragma unroll
        for (int i = 0; i < 8; i++)
            #pragma unroll
            for (int j = 0; j < 4; j++)
                if (ty + 16 * i == chunk * TSK + tx + 16 * j) acc[i][j] = 0.0f;
    }

    float* cv = smem;                                     // [128][32]
    int*   ci = reinterpret_cast<int*>(smem) + 128 * 32;

    // ---- Pass 1: row-wise top-2 (q rows of ti vs this 64-col chunk) ----
    __syncthreads();   // done with tiles; reuse smem
    #pragma unroll
    for (int i = 0; i < 8; i++) {
        float v1 = -INFINITY, v2 = -INFINITY;
        int   i1 = 0x7fffffff, i2 = 0x7fffffff;
        #pragma unroll
        for (int j = 0; j < 4; j++)
            top2_update(acc[i][j], kbase + tx + 16 * j, v1, i1, v2, i2);
        int r = ty + 16 * i;
        cv[r * 32 + tx * 2]     = v1; ci[r * 32 + tx * 2]     = i1;
        cv[r * 32 + tx * 2 + 1] = v2; ci[r * 32 + tx * 2 + 1] = i2;
    }
    __syncthreads();
    {
        // 2 threads per row: each scans 16 slots, then shfl_xor(1) merge.
        const int row  = tid >> 1;          // 0..127
        const int half = tid & 1;
        float V1 = -INFINITY, V2 = -INFINITY;
        int   I1 = 0x7fffffff, I2 = 0x7fffffff;
        #pragma unroll 8
        for (int c = 0; c < 16; c++)
            top2_update(cv[row * 32 + half * 16 + c],
                        ci[row * 32 + half * 16 + c], V1, I1, V2, I2);
        float oV1 = __shfl_xor_sync(0xffffffffu, V1, 1);
        float oV2 = __shfl_xor_sync(0xffffffffu, V2, 1);
        int   oI1 = __shfl_xor_sync(0xffffffffu, I1, 1);
        int   oI2 = __shfl_xor_sync(0xffffffffu, I2, 1);
        top2_update(oV1, oI1, V1, I1, V2, I2);   // halves disjoint -> exact
        top2_update(oV2, oI2, V1, I1, V2, I2);
        if (half == 0) {
            size_t base = ((size_t)(b * MM + ibase + row) * 32 + (2 * tj + chunk)) * 2;
            g_cand[base]     = make_float2(V1, __int_as_float(I1));
            g_cand[base + 1] = make_float2(V2, __int_as_float(I2));
        }
    }

    // ---- Pass 2: col-wise top-2 (k rows of this chunk vs 128 q cols) ----
    if (ti != tj) {
        __syncthreads();
        #pragma unroll
        for (int j = 0; j < 4; j++) {
            float v1 = -INFINITY, v2 = -INFINITY;
            int   i1 = 0x7fffffff, i2 = 0x7fffffff;
            #pragma unroll
            for (int i = 0; i < 8; i++)
                top2_update(acc[i][j], ibase + ty + 16 * i, v1, i1, v2, i2);
            int c = tx + 16 * j;    // 0..63
            cv[c * 32 + ty * 2]     = v1; ci[c * 32 + ty * 2]     = i1;
            cv[c * 32 + ty * 2 + 1] = v2; ci[c * 32 + ty * 2 + 1] = i2;
        }
        __syncthreads();
        if (tid < 2 * TSK) {
            const int row  = tid >> 1;      // 0..63
            const int half = tid & 1;
            float V1 = -INFINITY, V2 = -INFINITY;
            int   I1 = 0x7fffffff, I2 = 0x7fffffff;
            #pragma unroll 8
            for (int c = 0; c < 16; c++)
                top2_update(cv[row * 32 + half * 16 + c],
                            ci[row * 32 + half * 16 + c], V1, I1, V2, I2);
            float oV1 = __shfl_xor_sync(0xffffffffu, V1, 1);
            float oV2 = __shfl_xor_sync(0xffffffffu, V2, 1);
            int   oI1 = __shfl_xor_sync(0xffffffffu, I1, 1);
            int   oI2 = __shfl_xor_sync(0xffffffffu, I2, 1);
            top2_update(oV1, oI1, V1, I1, V2, I2);
            top2_update(oV2, oI2, V1, I1, V2, I2);
            if (half == 0) {
                size_t base = ((size_t)(b * MM + kbase + row) * 32 + ti) * 2;
                g_cand[base]     = make_float2(V1, __int_as_float(I1));
                g_cand[base + 1] = make_float2(V2, __int_as_float(I2));
            }
        }
    }
}

// ---------------------------------------------------------------------------
// Kernel 3: per-row reduce of candidate slots -> top-2 -> symmetric scatter.
// One warp per row; lane L owns slot L (2 candidates).
// Valid slots for row in tile t: [0, t) from pass-2, [2t, 32) from pass-1.
// ---------------------------------------------------------------------------
__global__ void reduce_kernel(float* __restrict__ out) {
    int row  = blockIdx.x * 8 + (threadIdx.x >> 5);
    int lane = threadIdx.x & 31;
    int m = row & (MM - 1);
    int t = m >> 7;

    float v1 = -INFINITY, v2 = -INFINITY;
    int   i1 = 0x7fffffff, i2 = 0x7fffffff;
    bool valid = (lane < t) || (lane >= 2 * t);
    if (valid) {
        float4 c = reinterpret_cast<const float4*>(g_cand)[(size_t)row * 32 + lane];
        v1 = c.x; i1 = __float_as_int(c.y);
        top2_update(c.z, __float_as_int(c.w), v1, i1, v2, i2);
    }
    #pragma unroll
    for (int o = 16; o > 0; o >>= 1) {
        float ov1 = __shfl_xor_sync(0xffffffffu, v1, o);
        float ov2 = __shfl_xor_sync(0xffffffffu, v2, o);
        int   oi1 = __shfl_xor_sync(0xffffffffu, i1, o);
        int   oi2 = __shfl_xor_sync(0xffffffffu, i2, o);
        top2_merge(ov1, oi1, v1, i1, v2, i2);
        top2_merge(ov2, oi2, v1, i1, v2, i2);
    }
    if (lane == 0) {
        int b = row >> 11;
        float* O = out + (size_t)b * MM * MM;
        atomicAdd(O + (size_t)m * MM + i1, 0.5f * v1);
        atomicAdd(O + (size_t)i1 * MM + m, 0.5f * v1);
        atomicAdd(O + (size_t)m * MM + i2, 0.5f * v2);
        atomicAdd(O + (size_t)i2 * MM + m, 0.5f * v2);
    }
}

// ---------------------------------------------------------------------------
extern "C" void kernel_launch(void* const* d_in, const int* in_sizes, int n_in,
                              void* d_out, int out_size) {
    const float* x = (const float*)d_in[0];
    float* out = (float*)d_out;

    normalize_kernel<<<(BB * MM) / 8, 256>>>(x);

    cudaFuncSetAttribute(pair_kernel,
                         cudaFuncAttributeMaxDynamicSharedMemorySize, SMEM_BYTES);
    dim3 grid(NPAIR, 2, BB);
    pair_kernel<<<grid, 256, SMEM_BYTES>>>(out);

    reduce_kernel<<<(BB * MM) / 8, 256>>>(out);
}